// round 10
// baseline (speedup 1.0000x reference)
#include <cuda_runtime.h>

// Fused cosine-score attention, single query. Two kernels.
// stage1 (proven best ~24.5-24.8us across 4 variants = memory-system ceiling
//   for this pattern): warp-per-row streaming over keys (128 MB), q + acc in
//   registers, block smem tree reduce -> 148 block partials (606 KB).
// stage2: warp-per-column reduction of the partials — no smem, no
//   __syncthreads (the old 5-barrier smem tree was the 4.9us culprit).

#define NBLK 148
#define NTHR 512
#define WPB  (NTHR / 32)           // 16 warps per block
#define NWARPS (NBLK * WPB)        // 2368
#define H 1024
#define HV4 (H / 4)                // 256 float4 per row

__device__ float4 g_partial[NBLK][HV4];   // 606 KB scratch

__global__ __launch_bounds__(NTHR, 1)
void bahdanau_stage1(const float* __restrict__ q,
                     const float* __restrict__ keys, int S) {
    const int wib  = threadIdx.x >> 5;
    const int warp = blockIdx.x * WPB + wib;
    const int lane = threadIdx.x & 31;

    __shared__ float4 red[8][HV4];   // 32 KB, reused across reduction phases

    // q slice for this lane + |q|
    const float4* q4 = (const float4*)q;
    float4 qv[8];
    float qss = 0.f;
#pragma unroll
    for (int i = 0; i < 8; i++) {
        qv[i] = q4[i * 32 + lane];
        qss += qv[i].x * qv[i].x + qv[i].y * qv[i].y +
               qv[i].z * qv[i].z + qv[i].w * qv[i].w;
    }
#pragma unroll
    for (int o = 16; o; o >>= 1) qss += __shfl_xor_sync(0xffffffffu, qss, o);
    const float inv_qn = rsqrtf(qss);

    float4 acc[8];
#pragma unroll
    for (int i = 0; i < 8; i++) acc[i] = make_float4(0.f, 0.f, 0.f, 0.f);

    for (int s = warp; s < S; s += NWARPS) {
        const float4* row = (const float4*)(keys + (size_t)s * H);
        float4 kv[8];
        float dot = 0.f, kss = 0.f;
#pragma unroll
        for (int i = 0; i < 8; i++) {
            kv[i] = row[i * 32 + lane];
            dot += kv[i].x * qv[i].x + kv[i].y * qv[i].y +
                   kv[i].z * qv[i].z + kv[i].w * qv[i].w;
            kss += kv[i].x * kv[i].x + kv[i].y * kv[i].y +
                   kv[i].z * kv[i].z + kv[i].w * kv[i].w;
        }
#pragma unroll
        for (int o = 16; o; o >>= 1) {
            dot += __shfl_xor_sync(0xffffffffu, dot, o);
            kss += __shfl_xor_sync(0xffffffffu, kss, o);
        }
        const float score = dot * inv_qn * rsqrtf(kss);
#pragma unroll
        for (int i = 0; i < 8; i++) {
            acc[i].x += score * kv[i].x;
            acc[i].y += score * kv[i].y;
            acc[i].z += score * kv[i].z;
            acc[i].w += score * kv[i].w;
        }
    }

    // Block tree reduction: 16 -> 8 -> 4 -> 2 -> 1 warps.
#pragma unroll
    for (int half = 8; half >= 1; half >>= 1) {
        if (wib >= half && wib < 2 * half) {
#pragma unroll
            for (int i = 0; i < 8; i++)
                red[wib - half][i * 32 + lane] = acc[i];
        }
        __syncthreads();
        if (wib < half) {
#pragma unroll
            for (int i = 0; i < 8; i++) {
                float4 v = red[wib][i * 32 + lane];
                acc[i].x += v.x; acc[i].y += v.y;
                acc[i].z += v.z; acc[i].w += v.w;
            }
        }
        __syncthreads();
    }

    if (wib == 0) {
#pragma unroll
        for (int i = 0; i < 8; i++)
            g_partial[blockIdx.x][i * 32 + lane] = acc[i];
    }
}

// stage2: out[h] = sum_{b<148} g_partial[b][h].
// One warp per column h; lane l sums rows l, l+32, ..., then shuffle-reduce.
// No shared memory, no __syncthreads.
__global__ __launch_bounds__(512)
void bahdanau_stage2(float* __restrict__ out) {
    const int warp = (blockIdx.x * 512 + threadIdx.x) >> 5;   // 0..1023 = col
    const int lane = threadIdx.x & 31;
    const float* part = (const float*)g_partial;

    float s = 0.f;
#pragma unroll
    for (int b = 0; b < 5; b++) {       // 5*32 = 160 >= 148
        int p = lane + b * 32;
        if (p < NBLK) s += part[(size_t)p * H + warp];
    }
#pragma unroll
    for (int o = 16; o; o >>= 1) s += __shfl_xor_sync(0xffffffffu, s, o);
    if (lane == 0) out[warp] = s;
}

extern "C" void kernel_launch(void* const* d_in, const int* in_sizes, int n_in,
                              void* d_out, int out_size) {
    const float* q    = (const float*)d_in[0];   // [1, 1024]
    const float* keys = (const float*)d_in[1];   // [S, 1024]
    const int S = in_sizes[1] / H;

    bahdanau_stage1<<<NBLK, NTHR>>>(q, keys, S);
    bahdanau_stage2<<<64, 512>>>((float*)d_out);  // 1024 warps, one per column
}